// round 16
// baseline (speedup 1.0000x reference)
#include <cuda_runtime.h>
#include <cuda_bf16.h>
#include <cfloat>

#define NN 2048
#define FF 64
#define KTOP 8
#define OUT_ROW ((KTOP + 1) * FF)   // 576

#define NBINS 512
#define BIN_HI 4.25f
#define BIN_W  (8.5f / (float)NBINS)
#define BIN_INVW ((float)NBINS / 8.5f)

#define SSTAGE 512
#define BATCH 8

// Per-feature candidate lists, descending value-bins (split arrays).
__device__ float g_xval[FF * NN];
__device__ int   g_off [FF * NN];

__device__ __forceinline__ int bin_of(float v) {
    int b = (int)((BIN_HI - v) * BIN_INVW);
    return max(0, min(NBINS - 1, b));
}
// Upper bound (>=0) on adj*x for ALL candidates at positions after one whose
// x-value is v (same bin or later bins; adj in [0,1)).
__device__ __forceinline__ float remaining_bound0(float v) {
    int b = bin_of(v);
    float e = (b == 0) ? FLT_MAX : (BIN_HI - (float)b * BIN_W + 1e-3f);
    return fmaxf(e, 0.0f);
}

// ---------------------------------------------------------------------------
// Kernel 1: per-feature bucket binning, 4 blocks per feature (R13-proven).
// ---------------------------------------------------------------------------
__global__ void __launch_bounds__(512) bin_cols_kernel(const float* __restrict__ x) {
    __shared__ float sx[NN];
    __shared__ int   cnt4[4][NBINS];
    __shared__ int   sa[NBINS];
    __shared__ int   sb[NBINS];
    __shared__ int   cur[NBINS];

    const int f   = blockIdx.x >> 2;
    const int q   = blockIdx.x & 3;
    const int tid = threadIdx.x;

#pragma unroll
    for (int c = 0; c < 4; c++) cnt4[c][tid] = 0;
    __syncthreads();

    float v0 = __ldg(&x[(0 * 512 + tid) * FF + f]);
    float v1 = __ldg(&x[(1 * 512 + tid) * FF + f]);
    float v2 = __ldg(&x[(2 * 512 + tid) * FF + f]);
    float v3 = __ldg(&x[(3 * 512 + tid) * FF + f]);
    sx[0 * 512 + tid] = v0;
    sx[1 * 512 + tid] = v1;
    sx[2 * 512 + tid] = v2;
    sx[3 * 512 + tid] = v3;
    atomicAdd(&cnt4[0][bin_of(v0)], 1);
    atomicAdd(&cnt4[1][bin_of(v1)], 1);
    atomicAdd(&cnt4[2][bin_of(v2)], 1);
    atomicAdd(&cnt4[3][bin_of(v3)], 1);
    __syncthreads();

    const int total = cnt4[0][tid] + cnt4[1][tid] + cnt4[2][tid] + cnt4[3][tid];
    sa[tid] = total;
    __syncthreads();
    int* src = sa; int* dst = sb;
    for (int d = 1; d < NBINS; d <<= 1) {
        dst[tid] = src[tid] + ((tid >= d) ? src[tid - d] : 0);
        __syncthreads();
        int* t = src; src = dst; dst = t;
    }
    {
        int off = src[tid] - total;
        for (int c = 0; c < q; c++) off += cnt4[c][tid];
        cur[tid] = off;
    }
    __syncthreads();

    {
        const int i = q * 512 + tid;
        const float v = sx[i];
        const int pos = atomicAdd(&cur[bin_of(v)], 1);
        g_xval[(size_t)f * NN + pos] = v;
        g_off [(size_t)f * NN + pos] = i * NN;
    }
}

// ---------------------------------------------------------------------------
// Kernel 2: pruned top-8 scan (champion loop, hardened + de-serialized).
// One warp per (f, 32 consecutive m); 128-thread blocks share f; grid 1024.
// ---------------------------------------------------------------------------
__global__ void __launch_bounds__(128, 8) topk_scan_kernel(
        const float* __restrict__ adj,
        const float* __restrict__ x,
        float* __restrict__ out) {
    __shared__ float sxv[SSTAGE];   // 2 KB
    __shared__ int   soff[SSTAGE];  // 2 KB

    const int f    = blockIdx.x >> 4;
    const int mg   = (blockIdx.x & 15) * 4 + (threadIdx.x >> 5);
    const int lane = threadIdx.x & 31;
    const int m    = mg * 32 + lane;

    // adj L2 prewarm (fire-and-forget; 128 x 128B lines = block's 16KB slice)
    {
        const char* pw = (const char*)adj
                       + (size_t)blockIdx.x * 16384 + (size_t)threadIdx.x * 128;
        asm volatile("prefetch.global.L2 [%0];" :: "l"(pw));
    }

    const float* __restrict__ gxv = g_xval + (size_t)f * NN;
    const int*   __restrict__ gof = g_off  + (size_t)f * NN;
    const float* __restrict__ acol = adj + m;

    float a0[BATCH], a1[BATCH], a2[BATCH], a3[BATCH];

    // --- EARLY initial prefetch: offsets for candidates 0..31 via one
    // coalesced load + shuffles; 32 adj LDGs issue BEFORE staging/sync. ---
    {
        int lo = __ldg(&gof[lane]);
#pragma unroll
        for (int c = 0; c < BATCH; c++)
            a0[c] = __ldg(acol + __shfl_sync(0xffffffffu, lo, c));
#pragma unroll
        for (int c = 0; c < BATCH; c++)
            a1[c] = __ldg(acol + __shfl_sync(0xffffffffu, lo, BATCH + c));
#pragma unroll
        for (int c = 0; c < BATCH; c++)
            a2[c] = __ldg(acol + __shfl_sync(0xffffffffu, lo, 2 * BATCH + c));
#pragma unroll
        for (int c = 0; c < BATCH; c++)
            a3[c] = __ldg(acol + __shfl_sync(0xffffffffu, lo, 3 * BATCH + c));
    }

    // Stage candidate list (2 arrays x 128 float4 => 1 each per thread)
    {
        const float4* s1 = (const float4*)gxv;
        const float4* s2 = (const float4*)gof;
        float4* d1 = (float4*)sxv;
        float4* d2 = (float4*)soff;
        for (int i = threadIdx.x; i < SSTAGE / 4; i += 128) {
            d1[i] = __ldg(s1 + i);
            d2[i] = __ldg(s2 + i);
        }
    }
    __syncthreads();

    float arr[KTOP];
#pragma unroll
    for (int j = 0; j < KTOP; j++) arr[j] = -FLT_MAX;

#define PREF(AB, b) do {                                                    \
    _Pragma("unroll")                                                       \
    for (int c = 0; c < BATCH; c++)                                         \
        AB[c] = __ldg(acol + soff[(b) + c]);                                \
    } while (0)

#define PROC(AB, b) do {                                                    \
    float v[BATCH];                                                         \
    _Pragma("unroll")                                                       \
    for (int c = 0; c < BATCH; c++) v[c] = AB[c] * sxv[(b) + c];            \
    float m01 = fmaxf(v[0], v[1]), m23 = fmaxf(v[2], v[3]);                 \
    float m45 = fmaxf(v[4], v[5]), m67 = fmaxf(v[6], v[7]);                 \
    float vmax = fmaxf(fmaxf(m01, m23), fmaxf(m45, m67));                   \
    if (__any_sync(0xffffffffu, vmax > arr[KTOP - 1])) {                    \
        _Pragma("unroll")                                                   \
        for (int c = 0; c < BATCH; c++) {                                   \
            float keep = v[c];                                              \
            _Pragma("unroll")                                               \
            for (int j = 0; j < KTOP; j++) {                                \
                float mx = fmaxf(arr[j], keep);                             \
                keep     = fminf(arr[j], keep);                             \
                arr[j]   = mx;                                              \
            } } } } while (0)

// Bound computed inline from the last-processed candidate's x value.
#define TERM(b) (!__any_sync(0xffffffffu,                                   \
                 remaining_bound0(sxv[(b) + BATCH - 1]) > arr[KTOP - 1]))

    int base = 0;
    bool fin = false;

    // Steady state: 32 loads in flight; termination voted every 2 batches.
    // Guard base+8*BATCH ensures every PREF target stays within SSTAGE.
    while (base + 8 * BATCH <= SSTAGE) {
        PROC(a0, base); PREF(a0, base + 4 * BATCH); base += BATCH;
        PROC(a1, base); PREF(a1, base + 4 * BATCH);
        if (TERM(base)) { fin = true; base += BATCH; break; }
        base += BATCH;
        PROC(a2, base); PREF(a2, base + 4 * BATCH); base += BATCH;
        PROC(a3, base); PREF(a3, base + 4 * BATCH);
        if (TERM(base)) { fin = true; base += BATCH; break; }
        base += BATCH;
    }

    if (!fin) {   // guard exit at base=480: buffers hold batches 480..511
        PROC(a0, base); fin = TERM(base); base += BATCH;
        if (!fin) { PROC(a1, base); fin = TERM(base); base += BATCH; }
        if (!fin) { PROC(a2, base); fin = TERM(base); base += BATCH; }
        if (!fin) { PROC(a3, base); fin = TERM(base); base += BATCH; }
    }

    // Global fallback (rarely reached; preserves exactness)
    while (!fin && base + BATCH <= NN) {
        float xg[BATCH];
#pragma unroll
        for (int c = 0; c < BATCH; c++) {
            a0[c] = __ldg(acol + __ldg(&gof[base + c]));
            xg[c] = __ldg(&gxv[base + c]);
        }
#pragma unroll
        for (int c = 0; c < BATCH; c++) {
            float v = a0[c] * xg[c];
            if (__any_sync(0xffffffffu, v > arr[KTOP - 1])) {
                float keep = v;
#pragma unroll
                for (int j = 0; j < KTOP; j++) {
                    float mx = fmaxf(arr[j], keep);
                    keep     = fminf(arr[j], keep);
                    arr[j]   = mx;
                }
            }
        }
        if (!__any_sync(0xffffffffu,
                        remaining_bound0(xg[BATCH - 1]) > arr[KTOP - 1]))
            fin = true;
        base += BATCH;
    }
#undef PREF
#undef PROC
#undef TERM

    // out[m, 1+j, f]
    float* o = out + (size_t)m * OUT_ROW + FF + f;
#pragma unroll
    for (int j = 0; j < KTOP; j++) o[j * FF] = arr[j];

    // k=0 slice: out[m, 0, f] = x[m, f]
    out[(size_t)m * OUT_ROW + f] = __ldg(&x[m * FF + f]);
}

extern "C" void kernel_launch(void* const* d_in, const int* in_sizes, int n_in,
                              void* d_out, int out_size) {
    const float* x   = (const float*)d_in[0];
    const float* adj = (const float*)d_in[1];
    if (in_sizes[0] == NN * NN) {
        adj = (const float*)d_in[0];
        x   = (const float*)d_in[1];
    }
    float* out = (float*)d_out;

    // 64 f * 4 chunks = 256 blocks of 512 threads
    bin_cols_kernel<<<256, 512>>>(x);

    // 64 f * 16 blocks/f = 1024 blocks of 128 threads (4 warps each)
    topk_scan_kernel<<<1024, 128>>>(adj, x, out);
}

// round 17
// speedup vs baseline: 1.0088x; 1.0088x over previous
#include <cuda_runtime.h>
#include <cuda_bf16.h>
#include <cfloat>

#define NN 2048
#define FF 64
#define KTOP 8
#define OUT_ROW ((KTOP + 1) * FF)   // 576

#define NBINS 512
#define BIN_HI 4.25f
#define BIN_W  (8.5f / (float)NBINS)
#define BIN_INVW ((float)NBINS / 8.5f)

#define SSTAGE 512
#define BATCH 8

// Per-feature candidate lists, descending value-bins.
// g_pair: (x value, adj row element-offset n*NN as float bits)
// g_bnd : max(bin upper edge, 0) -> bound on ALL later products
__device__ float2 g_pair[FF * NN];   // 1 MB
__device__ float  g_bnd [FF * NN];   // 512 KB

__device__ __forceinline__ int bin_of(float v) {
    int b = (int)((BIN_HI - v) * BIN_INVW);
    return max(0, min(NBINS - 1, b));
}
__device__ __forceinline__ float remaining_bound(float v) {
    int b = bin_of(v);
    return (b == 0) ? FLT_MAX : (BIN_HI - (float)b * BIN_W + 1e-3f);
}

// ---------------------------------------------------------------------------
// Kernel 1: per-feature bucket binning, 4 blocks per feature (R13-proven).
// Block (f, q) loads the whole column, histograms per 512-row chunk,
// computes deterministic per-chunk bin offsets, scatters ONLY chunk q.
// ---------------------------------------------------------------------------
__global__ void __launch_bounds__(512) bin_cols_kernel(const float* __restrict__ x) {
    __shared__ float sx[NN];
    __shared__ int   cnt4[4][NBINS];
    __shared__ int   sa[NBINS];
    __shared__ int   sb[NBINS];
    __shared__ int   cur[NBINS];

    const int f   = blockIdx.x >> 2;
    const int q   = blockIdx.x & 3;
    const int tid = threadIdx.x;      // 512 threads

#pragma unroll
    for (int c = 0; c < 4; c++) cnt4[c][tid] = 0;
    __syncthreads();

    float v0 = __ldg(&x[(0 * 512 + tid) * FF + f]);
    float v1 = __ldg(&x[(1 * 512 + tid) * FF + f]);
    float v2 = __ldg(&x[(2 * 512 + tid) * FF + f]);
    float v3 = __ldg(&x[(3 * 512 + tid) * FF + f]);
    sx[0 * 512 + tid] = v0;
    sx[1 * 512 + tid] = v1;
    sx[2 * 512 + tid] = v2;
    sx[3 * 512 + tid] = v3;
    atomicAdd(&cnt4[0][bin_of(v0)], 1);
    atomicAdd(&cnt4[1][bin_of(v1)], 1);
    atomicAdd(&cnt4[2][bin_of(v2)], 1);
    atomicAdd(&cnt4[3][bin_of(v3)], 1);
    __syncthreads();

    const int total = cnt4[0][tid] + cnt4[1][tid] + cnt4[2][tid] + cnt4[3][tid];
    sa[tid] = total;
    __syncthreads();
    int* src = sa; int* dst = sb;
    for (int d = 1; d < NBINS; d <<= 1) {
        dst[tid] = src[tid] + ((tid >= d) ? src[tid - d] : 0);
        __syncthreads();
        int* t = src; src = dst; dst = t;
    }
    {
        int off = src[tid] - total;
        for (int c = 0; c < q; c++) off += cnt4[c][tid];
        cur[tid] = off;
    }
    __syncthreads();

    {
        const int i = q * 512 + tid;
        const float v = sx[i];
        const int pos = atomicAdd(&cur[bin_of(v)], 1);
        g_pair[(size_t)f * NN + pos] = make_float2(v, __int_as_float(i * NN));
        g_bnd [(size_t)f * NN + pos] = fmaxf(remaining_bound(v), 0.0f);
    }
}

// ---------------------------------------------------------------------------
// Kernel 2: pruned top-8 scan (champion loop), combined float2 staging,
// fire-and-forget L2 prefetch of the block's adj slice, OOB-safe guard.
// One warp per (f, 32 consecutive m); 128-thread blocks share f; grid 1024.
// ---------------------------------------------------------------------------
__global__ void __launch_bounds__(128, 8) topk_scan_kernel(
        const float* __restrict__ adj,
        const float* __restrict__ x,
        float* __restrict__ out) {
    __shared__ float2 sp [SSTAGE];   // 4 KB: (xval, offset bits)
    __shared__ float  sbd[SSTAGE];   // 2 KB

    const int f    = blockIdx.x >> 4;
    const int mg   = (blockIdx.x & 15) * 4 + (threadIdx.x >> 5);
    const int lane = threadIdx.x & 31;
    const int m    = mg * 32 + lane;

    // adj L2 prewarm (fire-and-forget; 128 x 128B lines = block's 16KB slice)
    {
        const char* pw = (const char*)adj
                       + (size_t)blockIdx.x * 16384 + (size_t)threadIdx.x * 128;
        asm volatile("prefetch.global.L2 [%0];" :: "l"(pw));
    }

    const float2* __restrict__ gp = g_pair + (size_t)f * NN;
    const float*  __restrict__ gb = g_bnd  + (size_t)f * NN;

    {
        const float4* s1 = (const float4*)gp;    // 256 float4
        const float4* s2 = (const float4*)gb;    // 128 float4
        float4* d1 = (float4*)sp;
        float4* d2 = (float4*)sbd;
        for (int i = threadIdx.x; i < SSTAGE / 2; i += 128)
            d1[i] = __ldg(s1 + i);
        for (int i = threadIdx.x; i < SSTAGE / 4; i += 128)
            d2[i] = __ldg(s2 + i);
    }
    __syncthreads();

    const float* __restrict__ acol = adj + m;

    float arr[KTOP];
#pragma unroll
    for (int j = 0; j < KTOP; j++) arr[j] = -FLT_MAX;

    float a0[BATCH], a1[BATCH], a2[BATCH], a3[BATCH];

#define PREF(AB, b) do {                                                    \
    _Pragma("unroll")                                                       \
    for (int c = 0; c < BATCH; c++)                                         \
        AB[c] = __ldg(acol + __float_as_int(sp[(b) + c].y));                \
    } while (0)

// Batch vote; on pass, insert all 8 unconditionally (chain is a no-op for
// values below arr[7]).
#define PROC(AB, b) do {                                                    \
    float v[BATCH];                                                         \
    _Pragma("unroll")                                                       \
    for (int c = 0; c < BATCH; c++) v[c] = AB[c] * sp[(b) + c].x;           \
    float m01 = fmaxf(v[0], v[1]), m23 = fmaxf(v[2], v[3]);                 \
    float m45 = fmaxf(v[4], v[5]), m67 = fmaxf(v[6], v[7]);                 \
    float vmax = fmaxf(fmaxf(m01, m23), fmaxf(m45, m67));                   \
    if (__any_sync(0xffffffffu, vmax > arr[KTOP - 1])) {                    \
        _Pragma("unroll")                                                   \
        for (int c = 0; c < BATCH; c++) {                                   \
            float keep = v[c];                                              \
            _Pragma("unroll")                                               \
            for (int j = 0; j < KTOP; j++) {                                \
                float mx = fmaxf(arr[j], keep);                             \
                keep     = fminf(arr[j], keep);                             \
                arr[j]   = mx;                                              \
            } } } } while (0)

#define TERM(b) (!__any_sync(0xffffffffu, sbd[(b) + BATCH - 1] > arr[KTOP - 1]))

    PREF(a0, 0); PREF(a1, BATCH); PREF(a2, 2 * BATCH); PREF(a3, 3 * BATCH);

    int base = 0;
    bool fin = false;

    // Steady state: 32 loads in flight. Guard keeps every PREF in-bounds:
    // max target = base + 3*BATCH (phase) + 4*BATCH + 7 = base + 63 <= 511.
    while (base + 8 * BATCH <= SSTAGE) {
        PROC(a0, base); PREF(a0, base + 4 * BATCH);
        if (TERM(base)) { fin = true; break; }
        base += BATCH;
        PROC(a1, base); PREF(a1, base + 4 * BATCH);
        if (TERM(base)) { fin = true; break; }
        base += BATCH;
        PROC(a2, base); PREF(a2, base + 4 * BATCH);
        if (TERM(base)) { fin = true; break; }
        base += BATCH;
        PROC(a3, base); PREF(a3, base + 4 * BATCH);
        if (TERM(base)) { fin = true; break; }
        base += BATCH;
    }

    if (!fin) {   // guard exit at base=448: buffers hold batches 448..479
        PROC(a0, base); fin = TERM(base); base += BATCH;
        if (!fin) { PROC(a1, base); fin = TERM(base); base += BATCH; }
        if (!fin) { PROC(a2, base); fin = TERM(base); base += BATCH; }
        if (!fin) { PROC(a3, base); fin = TERM(base); base += BATCH; }
        // remaining staged candidates 480..511, no prefetch pipeline
        while (!fin && base + BATCH <= SSTAGE) {
            PREF(a0, base);
            PROC(a0, base);
            fin = TERM(base);
            base += BATCH;
        }
    }

    // Global fallback (rarely reached; preserves exactness)
    while (!fin && base + BATCH <= NN) {
        float xg[BATCH];
#pragma unroll
        for (int c = 0; c < BATCH; c++) {
            float2 p = __ldg(&gp[base + c]);
            xg[c] = p.x;
            a0[c] = __ldg(acol + __float_as_int(p.y));
        }
#pragma unroll
        for (int c = 0; c < BATCH; c++) {
            float v = a0[c] * xg[c];
            if (__any_sync(0xffffffffu, v > arr[KTOP - 1])) {
                float keep = v;
#pragma unroll
                for (int j = 0; j < KTOP; j++) {
                    float mx = fmaxf(arr[j], keep);
                    keep     = fminf(arr[j], keep);
                    arr[j]   = mx;
                }
            }
        }
        float bd = __ldg(&gb[base + BATCH - 1]);
        if (!__any_sync(0xffffffffu, bd > arr[KTOP - 1])) fin = true;
        base += BATCH;
    }
#undef PREF
#undef PROC
#undef TERM

    // out[m, 1+j, f]
    float* o = out + (size_t)m * OUT_ROW + FF + f;
#pragma unroll
    for (int j = 0; j < KTOP; j++) o[j * FF] = arr[j];

    // k=0 slice: out[m, 0, f] = x[m, f]
    out[(size_t)m * OUT_ROW + f] = __ldg(&x[m * FF + f]);
}

extern "C" void kernel_launch(void* const* d_in, const int* in_sizes, int n_in,
                              void* d_out, int out_size) {
    const float* x   = (const float*)d_in[0];
    const float* adj = (const float*)d_in[1];
    if (in_sizes[0] == NN * NN) {
        adj = (const float*)d_in[0];
        x   = (const float*)d_in[1];
    }
    float* out = (float*)d_out;

    // 64 f * 4 chunks = 256 blocks of 512 threads
    bin_cols_kernel<<<256, 512>>>(x);

    // 64 f * 16 blocks/f = 1024 blocks of 128 threads (4 warps each)
    topk_scan_kernel<<<1024, 128>>>(adj, x, out);
}